// round 15
// baseline (speedup 1.0000x reference)
#include <cuda_runtime.h>
#include <cuda_fp16.h>
#include <cstdint>

#define BB 16
#define TT 128
#define VV 137
#define CC0 3
#define PADK 4
#define NCLS 226
#define VC (VV*CC0)       // 411
#define TVN (TT*VV)       // 17536 = 137 * 128
#define NPAD 18816        // 548 halo + 17536 + 548 halo + slack
#define HALO 548
#define NT 137            // conv n-tiles of 128
#define VPAD 144          // gmm K/N padding
#define WPAD 160          // gmm N padding (warp tile 80 x 2)

// ---------------- scratch (static device memory; no allocations) ----------------
__device__ __half g_xT[(size_t)BB*NPAD*128];          // conv B operand (single fp16)
__device__ __half g_xgh[(size_t)BB*TT*128*VPAD];      // gmm A operand (hi)
__device__ __half g_xgl[(size_t)BB*TT*128*VPAD];      // gmm A operand (lo)
__device__ __half g_A[(size_t)BB*TT*WPAD*VPAD];       // adjacency (single fp16)
__device__ float g_xin[(size_t)BB*CC0*TT*VV];
__device__ __half g_wh[9*256*128];
__device__ __half g_wl[9*256*128];
__device__ float g_partial[(size_t)BB*256*NT*4];
__device__ float g_scale[VC];
__device__ float g_shift[VC];
__device__ float g_pooled[BB*256];

// ======================= warp-MMA helpers (compute_103-safe) ====================
__device__ __forceinline__ uint32_t smem_to_u32(const void* p) {
    uint32_t a;
    asm("{ .reg .u64 t; cvta.to.shared.u64 t, %1; cvt.u32.u64 %0, t; }" : "=r"(a) : "l"(p));
    return a;
}
__device__ __forceinline__ void ldsm4(uint32_t* r, uint32_t addr) {
    asm volatile("ldmatrix.sync.aligned.m8n8.x4.shared.b16 {%0,%1,%2,%3}, [%4];"
        : "=r"(r[0]), "=r"(r[1]), "=r"(r[2]), "=r"(r[3]) : "r"(addr));
}
__device__ __forceinline__ void mma_f16(float* d, const uint32_t* a,
                                        uint32_t b0, uint32_t b1) {
    asm volatile("mma.sync.aligned.m16n8k16.row.col.f32.f16.f16.f32 "
        "{%0,%1,%2,%3}, {%4,%5,%6,%7}, {%8,%9}, {%0,%1,%2,%3};"
        : "+f"(d[0]), "+f"(d[1]), "+f"(d[2]), "+f"(d[3])
        : "r"(a[0]), "r"(a[1]), "r"(a[2]), "r"(a[3]), "r"(b0), "r"(b1));
}
__device__ __forceinline__ void split_f16(float v, __half& h, __half& l) {
    h = __float2half_rn(v);
    l = __float2half_rn(v - __half2float(h));
}
__device__ __forceinline__ void cpa16(uint32_t dst, const void* src) {
    asm volatile("cp.async.cg.shared.global [%0], [%1], 16;" :: "r"(dst), "l"(src));
}
#define CP_COMMIT() asm volatile("cp.async.commit_group;" ::: "memory")
#define CP_WAIT1()  asm volatile("cp.async.wait_group 1;" ::: "memory")
#define CP_WAIT0()  asm volatile("cp.async.wait_group 0;" ::: "memory")

// ---------------- adjacency -> fp16 [bt][w(WPAD)][v(VPAD)] ----------------------
__global__ __launch_bounds__(256) void adj_kernel(const float* __restrict__ X) {
    int bt = blockIdx.x;
    __shared__ float px[VV*3];
    const float* src = X + (size_t)bt * VV * CC0;
    for (int i = threadIdx.x; i < VV*3; i += 256) px[i] = src[i];
    __syncthreads();
    const size_t base = (size_t)bt * WPAD * VPAD;
    for (int i = threadIdx.x; i < VV*VV; i += 256) {
        int w = i / VV, v = i % VV;
        float dx = px[v*3+0] - px[w*3+0];
        float dy = px[v*3+1] - px[w*3+1];
        float dz = px[v*3+2] - px[w*3+2];
        float d = sqrtf(dx*dx + dy*dy + dz*dz);
        g_A[base + (size_t)w * VPAD + v] = __float2half_rn(__expf(-2.0f * d));
    }
}

// ---------------- BN stats / apply ----------------------------------------------
__global__ __launch_bounds__(256) void bn_stats(const float* __restrict__ X,
                                                const float* __restrict__ gamma,
                                                const float* __restrict__ beta) {
    int ch = blockIdx.x;
    int v = ch / CC0, c = ch % CC0;
    float s = 0.f, s2 = 0.f;
    for (int i = threadIdx.x; i < BB*TT; i += 256) {
        float x = X[((size_t)i * VV + v) * CC0 + c];
        s += x; s2 += x * x;
    }
    __shared__ float sh1[8], sh2[8];
    int lane = threadIdx.x & 31, wid = threadIdx.x >> 5;
    #pragma unroll
    for (int o = 16; o > 0; o >>= 1) {
        s  += __shfl_xor_sync(0xffffffffu, s, o);
        s2 += __shfl_xor_sync(0xffffffffu, s2, o);
    }
    if (lane == 0) { sh1[wid] = s; sh2[wid] = s2; }
    __syncthreads();
    if (wid == 0) {
        s  = (lane < 8) ? sh1[lane] : 0.f;
        s2 = (lane < 8) ? sh2[lane] : 0.f;
        #pragma unroll
        for (int o = 4; o > 0; o >>= 1) {
            s  += __shfl_xor_sync(0xffffffffu, s, o);
            s2 += __shfl_xor_sync(0xffffffffu, s2, o);
        }
        if (lane == 0) {
            float inv = 1.0f / (BB*TT);
            float mean = s * inv;
            float var = s2 * inv - mean * mean;
            float sc = gamma[ch] * rsqrtf(var + 1e-5f);
            g_scale[ch] = sc;
            g_shift[ch] = beta[ch] - mean * sc;
        }
    }
}

__global__ __launch_bounds__(256) void bn_apply(const float* __restrict__ X) {
    int idx = blockIdx.x * 256 + threadIdx.x;
    if (idx >= BB*TT*VV*CC0) return;
    int c = idx % CC0;
    int v = (idx / CC0) % VV;
    int t = (idx / (CC0*VV)) % TT;
    int b = idx / (CC0*VV*TT);
    int ch = v * CC0 + c;
    g_xin[(((size_t)b * CC0 + c) * TT + t) * VV + v] = X[idx] * g_scale[ch] + g_shift[ch];
}

// ---------------- conv0 (tiny, CUDA cores, Cin=3, no relu) -----------------------
__global__ __launch_bounds__(256) void conv0_kernel(const float* __restrict__ x,
                                                    const float* __restrict__ w,
                                                    const float* __restrict__ bias) {
    const int t = blockIdx.x, b = blockIdx.y;
    __shared__ float ws[3*9*64];
    __shared__ float xs[3*9*160];
    const int tid = threadIdx.x;
    const int vg = tid & 31, og = tid >> 5;
    unsigned long long acc[4][5];
    #pragma unroll
    for (int u = 0; u < 4; u++)
        #pragma unroll
        for (int j = 0; j < 5; j++) acc[u][j] = 0ull;
    for (int i = tid; i < 3*9*64; i += 256) {
        int o = i & 63; int r = i >> 6; int k = r % 9; int ci = r / 9;
        ws[i] = w[((size_t)o * 3 + ci) * 9 + k];
    }
    for (int i = tid; i < 3*9*160; i += 256) {
        int v = i % 160; int r = i / 160; int k = r % 9; int ci = r / 9;
        int tt = t + k - PADK;
        float val = 0.f;
        if (v < VV && tt >= 0 && tt < TT)
            val = x[(((size_t)b * 3 + ci) * TT + tt) * VV + v];
        xs[i] = val;
    }
    __syncthreads();
    #pragma unroll
    for (int ci = 0; ci < 3; ci++) {
        #pragma unroll
        for (int k = 0; k < 9; k++) {
            const float* xrow = &xs[(ci*9 + k) * 160];
            const float* wrow = &ws[(ci*9 + k) * 64 + og * 8];
            unsigned long long xv2[5];
            #pragma unroll
            for (int j = 0; j < 5; j++) {
                float xv = xrow[vg + 32*j];
                asm("mov.b64 %0, {%1,%1};" : "=l"(xv2[j]) : "f"(xv));
            }
            #pragma unroll
            for (int u = 0; u < 4; u++) {
                unsigned long long w2 = *reinterpret_cast<const unsigned long long*>(&wrow[2*u]);
                #pragma unroll
                for (int j = 0; j < 5; j++)
                    asm("fma.rn.f32x2 %0, %1, %2, %0;" : "+l"(acc[u][j]) : "l"(w2), "l"(xv2[j]));
            }
        }
    }
    const size_t rb = (size_t)(b * TT + t) * 128;
    #pragma unroll
    for (int u = 0; u < 4; u++) {
        int o_lo = og*8 + 2*u;
        float b_lo = bias[o_lo], b_hi = bias[o_lo + 1];
        #pragma unroll
        for (int j = 0; j < 5; j++) {
            int v = vg + 32*j;
            if (v < VV) {
                float lo, hi;
                asm("mov.b64 {%0,%1}, %2;" : "=f"(lo), "=f"(hi) : "l"(acc[u][j]));
                lo += b_lo; hi += b_hi;
                __half h, l;
                split_f16(lo, h, l);
                size_t a0 = (rb + o_lo) * VPAD + v;
                g_xgh[a0] = h; g_xgl[a0] = l;
                split_f16(hi, h, l);
                size_t a1 = (rb + o_lo + 1) * VPAD + v;
                g_xgh[a1] = h; g_xgl[a1] = l;
            }
        }
    }
}

// ---------------- gmm_mma: per (b,t) D[c,w] = sum_v x[c,v] * A[w,v] --------------
// A-side: x split fp16 (2-term). B-side: adjacency single fp16.
template<int MFRAG>   // 1: Cin=64, 2: Cin=128
__global__ void __launch_bounds__(256, 1) gmm_mma() {
    extern __shared__ __align__(16) char smem[];
    const uint32_t sb = smem_to_u32(smem);
    const int Cin = MFRAG * 64;
    const int MT = MFRAG * 16;
    const uint32_t XSZ = (uint32_t)Cin * 112;
    const uint32_t ASZ = 160 * 112;
    const uint32_t STAGE = 2*XSZ + ASZ;
    const int bt = blockIdx.x;
    const int b = bt >> 7, t = bt & 127;
    const int tid = threadIdx.x, lane = tid & 31, wid = tid >> 5;
    const int wm = wid >> 1, wn = wid & 1;

    float acc[MFRAG][10][4];
    #pragma unroll
    for (int mi = 0; mi < MFRAG; mi++)
        #pragma unroll
        for (int n = 0; n < 10; n++)
            #pragma unroll
            for (int r = 0; r < 4; r++) acc[mi][n][r] = 0.f;

    const uint32_t a_lane = (uint32_t)(wm*MT + (lane & 15)) * 112 + (uint32_t)(lane >> 4) * 16;
    const uint32_t b_lane = (uint32_t)(wn*80 + (lane & 7) + ((lane >> 4) << 3)) * 112
                          + (uint32_t)((lane >> 3) & 1) * 16;

    auto prefetch = [&](int s) {
        const uint32_t st = sb + (uint32_t)(s & 1) * STAGE;
        const int k0 = s * 48;
        for (int i = tid; i < Cin*6; i += 256) {
            int r = i / 6, j = i % 6;
            uint32_t dst = st + (uint32_t)r * 112 + (uint32_t)j * 16;
            size_t src = ((size_t)bt * 128 + r) * VPAD + k0 + j * 8;
            cpa16(dst, g_xgh + src);
            cpa16(dst + XSZ, g_xgl + src);
        }
        for (int i = tid; i < 160*6; i += 256) {
            int r = i / 6, j = i % 6;
            uint32_t dst = st + 2*XSZ + (uint32_t)r * 112 + (uint32_t)j * 16;
            size_t src = ((size_t)bt * WPAD + r) * VPAD + k0 + j * 8;
            cpa16(dst, g_A + src);
        }
        CP_COMMIT();
    };

    prefetch(0);
    for (int s = 0; s < 3; s++) {
        if (s + 1 < 3) { prefetch(s + 1); CP_WAIT1(); } else { CP_WAIT0(); }
        __syncthreads();
        const uint32_t st = sb + (uint32_t)(s & 1) * STAGE;
        #pragma unroll
        for (int kk = 0; kk < 3; kk++) {
            const uint32_t koff = (uint32_t)kk * 32;
            uint32_t ah[MFRAG][4], al[MFRAG][4];
            #pragma unroll
            for (int mi = 0; mi < MFRAG; mi++) {
                uint32_t ao = a_lane + (uint32_t)mi * (16*112) + koff;
                ldsm4(ah[mi], st + ao);
                ldsm4(al[mi], st + XSZ + ao);
            }
            #pragma unroll
            for (int g = 0; g < 5; g++) {
                uint32_t bv[4];
                uint32_t bo = b_lane + (uint32_t)g * (16*112) + koff;
                ldsm4(bv, st + 2*XSZ + bo);
                #pragma unroll
                for (int mi = 0; mi < MFRAG; mi++)
                    #pragma unroll
                    for (int hh = 0; hh < 2; hh++) {
                        float* d = acc[mi][g*2 + hh];
                        mma_f16(d, ah[mi], bv[2*hh], bv[2*hh+1]);
                        mma_f16(d, al[mi], bv[2*hh], bv[2*hh+1]);
                    }
            }
        }
        __syncthreads();
    }

    // epilogue: write single fp16 g_xT[(b*NPAD + HALO + t*137 + w)*128 + c]
    const int mrow = lane >> 2, nc = (lane & 3) * 2;
    const size_t nbase = (size_t)b * NPAD + HALO + (size_t)t * VV;
    #pragma unroll
    for (int mi = 0; mi < MFRAG; mi++)
        #pragma unroll
        for (int h = 0; h < 2; h++) {
            int c = wm*MT + mi*16 + h*8 + mrow;
            #pragma unroll
            for (int g = 0; g < 5; g++)
                #pragma unroll
                for (int hh = 0; hh < 2; hh++)
                    #pragma unroll
                    for (int e = 0; e < 2; e++) {
                        int w = wn*80 + g*16 + hh*8 + nc + e;
                        if (w < VV)
                            g_xT[(nbase + w) * 128 + c] =
                                __float2half_rn(acc[mi][g*2+hh][h*2+e]);
                    }
        }
}

// ---------------- weight prep: fp32 [o][ci][k] -> split fp16 [k][OPAD][ci] ------
__global__ __launch_bounds__(256) void wprep(const float* __restrict__ w,
                                             int Cin, int Cout, int OPAD) {
    int idx = blockIdx.x * 256 + threadIdx.x;
    int total = 9 * OPAD * Cin;
    if (idx >= total) return;
    int ci = idx % Cin;
    int r = idx / Cin;
    int o = r % OPAD;
    int k = r / OPAD;
    float v = (o < Cout) ? w[((size_t)o * Cin + ci) * 9 + k] : 0.f;
    __half h, l; split_f16(v, h, l);
    g_wh[idx] = h; g_wl[idx] = l;
}

// ---------------- warp-MMA temporal conv, cp.async double-buffered --------------
// A-side: weights split fp16 (2-term). B-side: activations single fp16.
// M = MI*32 (o), N = 128 (n). 8 warps = 2(M) x 4(N).
template<int MI>   // 2: M=64 (layer1), 4: M=128 (layers 2/3)
__global__ void __launch_bounds__(256, 1) conv_mma(
    const float* __restrict__ bias, float* __restrict__ pout,
    int Cin, int Cout, int OPAD, int otiles)
{
    extern __shared__ __align__(16) char smem[];
    const uint32_t sb = smem_to_u32(smem);
    const int AROWS = MI * 32;
    const uint32_t ASZ = (uint32_t)AROWS * 144;
    const uint32_t BSZ = 128 * 144;
    const uint32_t STAGE = 2*ASZ + BSZ;
    const int tid = threadIdx.x;
    const int tileid = blockIdx.x / otiles;            // n tile
    const int o0 = (blockIdx.x - tileid * otiles) * AROWS;
    const int n0 = tileid * 128;
    const int b  = blockIdx.y;
    const int lane = tid & 31, wid = tid >> 5;
    const int wm = wid >> 2, wn = wid & 3;
    const int numC = Cin >> 6;
    const int S = 9 * numC;

    float acc[MI][4][4];
    #pragma unroll
    for (int mi = 0; mi < MI; mi++)
        #pragma unroll
        for (int ni = 0; ni < 4; ni++)
            #pragma unroll
            for (int r = 0; r < 4; r++) acc[mi][ni][r] = 0.f;

    const uint32_t a_lane = (uint32_t)(wm*(MI*16) + (lane & 15)) * 144 + (uint32_t)(lane >> 4) * 16;
    const uint32_t b_lane = (uint32_t)(wn*32 + (lane & 7) + ((lane >> 4) << 3)) * 144
                          + (uint32_t)((lane >> 3) & 1) * 16;

    auto prefetch = [&](int s) {
        const uint32_t st = sb + (uint32_t)(s & 1) * STAGE;
        const int k = s / numC;
        const int c0 = (s - k * numC) << 6;
        const long long brow = (long long)b * NPAD + HALO + n0 + (long long)(k - 4) * VV;
        for (int i = tid; i < AROWS*8; i += 256) {
            int r = i >> 3, ch = i & 7;
            uint32_t dst = st + (uint32_t)r * 144 + (uint32_t)ch * 16;
            size_t src = (size_t)(k * OPAD + o0 + r) * Cin + c0 + ch * 8;
            cpa16(dst, g_wh + src);
            cpa16(dst + ASZ, g_wl + src);
        }
        for (int i = tid; i < 128*8; i += 256) {
            int r = i >> 3, ch = i & 7;
            uint32_t dst = st + 2*ASZ + (uint32_t)r * 144 + (uint32_t)ch * 16;
            size_t src = (size_t)(brow + r) * 128 + c0 + ch * 8;
            cpa16(dst, g_xT + src);
        }
        CP_COMMIT();
    };

    prefetch(0);
    for (int s = 0; s < S; s++) {
        if (s + 1 < S) { prefetch(s + 1); CP_WAIT1(); } else { CP_WAIT0(); }
        __syncthreads();
        const uint32_t st = sb + (uint32_t)(s & 1) * STAGE;
        #pragma unroll
        for (int kk = 0; kk < 4; kk++) {
            const uint32_t koff = (uint32_t)kk * 32;
            uint32_t ah[MI][4], al[MI][4];
            #pragma unroll
            for (int mi = 0; mi < MI; mi++) {
                uint32_t ao = a_lane + (uint32_t)mi * (16*144) + koff;
                ldsm4(ah[mi], st + ao);
                ldsm4(al[mi], st + ASZ + ao);
            }
            uint32_t bv[2][4];
            #pragma unroll
            for (int g = 0; g < 2; g++) {
                uint32_t bo = b_lane + (uint32_t)g * (16*144) + koff;
                ldsm4(bv[g], st + 2*ASZ + bo);
            }
            #pragma unroll
            for (int mi = 0; mi < MI; mi++)
                #pragma unroll
                for (int g = 0; g < 2; g++)
                    #pragma unroll
                    for (int hh = 0; hh < 2; hh++) {
                        int ni = g*2 + hh;
                        mma_f16(acc[mi][ni], ah[mi], bv[g][2*hh], bv[g][2*hh+1]);
                        mma_f16(acc[mi][ni], al[mi], bv[g][2*hh], bv[g][2*hh+1]);
                    }
        }
        __syncthreads();
    }

    const int mrow = lane >> 2;
    const int ncol = (lane & 3) * 2;
    if (pout) {
        // layer 3: bias + relu + pooled partials per (b, o, tile, wn)
        #pragma unroll
        for (int mi = 0; mi < MI; mi++)
            #pragma unroll
            for (int h = 0; h < 2; h++) {
                int o = o0 + wm*(MI*16) + mi*16 + mrow + h*8;
                float bo = bias[o];
                float s = 0.f;
                #pragma unroll
                for (int ni = 0; ni < 4; ni++) {
                    s += fmaxf(acc[mi][ni][2*h+0] + bo, 0.f);
                    s += fmaxf(acc[mi][ni][2*h+1] + bo, 0.f);
                }
                s += __shfl_xor_sync(0xffffffffu, s, 1);
                s += __shfl_xor_sync(0xffffffffu, s, 2);
                if ((lane & 3) == 0)
                    pout[((size_t)(b * 256 + o) * NT + tileid) * 4 + wn] = s;
            }
    } else {
        // layers 1/2: bias + relu, write split fp16 x[bt][c][VPAD] for next gmm
        #pragma unroll
        for (int mi = 0; mi < MI; mi++)
            #pragma unroll
            for (int h = 0; h < 2; h++) {
                int o = o0 + wm*(MI*16) + mi*16 + mrow + h*8;
                if (o < Cout) {
                    float bo = bias[o];
                    #pragma unroll
                    for (int ni = 0; ni < 4; ni++)
                        #pragma unroll
                        for (int e = 0; e < 2; e++) {
                            int n = n0 + wn*32 + ni*8 + ncol + e;
                            float val = fmaxf(acc[mi][ni][2*h+e] + bo, 0.f);
                            __half hv, lv; split_f16(val, hv, lv);
                            int tt = n / VV, v = n - tt * VV;
                            size_t ad = ((size_t)(b * TT + tt) * 128 + o) * VPAD + v;
                            g_xgh[ad] = hv; g_xgl[ad] = lv;
                        }
                }
            }
    }
}

// ---------------- pool reduce + FC -----------------------------------------------
__global__ __launch_bounds__(256) void pool_reduce() {
    int idx = blockIdx.x * 256 + threadIdx.x;
    if (idx >= BB * 256) return;
    const float* p = &g_partial[(size_t)idx * NT * 4];
    float s = 0.f;
    for (int i = 0; i < NT * 4; i++) s += p[i];
    g_pooled[idx] = s * (1.0f / TVN);
}

__global__ __launch_bounds__(256) void fc_kernel(const float* __restrict__ fw,
                                                 const float* __restrict__ fb,
                                                 float* __restrict__ out) {
    int b = blockIdx.x;
    __shared__ float ps[256];
    ps[threadIdx.x] = g_pooled[b * 256 + threadIdx.x];
    __syncthreads();
    int n = threadIdx.x;
    if (n < NCLS) {
        float s = fb[n];
        const float* wr = &fw[(size_t)n * 256];
        #pragma unroll 8
        for (int c = 0; c < 256; c++) s += ps[c] * wr[c];
        out[b * NCLS + n] = s;
    }
}

// ---------------- launch ----------------------------------------------------------
extern "C" void kernel_launch(void* const* d_in, const int* in_sizes, int n_in,
                              void* d_out, int out_size) {
    const float* X     = (const float*)d_in[0];
    const float* gamma = (const float*)d_in[1];
    const float* beta  = (const float*)d_in[2];
    const float* w0 = (const float*)d_in[3];  const float* b0 = (const float*)d_in[4];
    const float* w1 = (const float*)d_in[5];  const float* b1 = (const float*)d_in[6];
    const float* w2 = (const float*)d_in[7];  const float* b2 = (const float*)d_in[8];
    const float* w3 = (const float*)d_in[9];  const float* b3 = (const float*)d_in[10];
    const float* fw = (const float*)d_in[11]; const float* fb = (const float*)d_in[12];
    float* out = (float*)d_out;

    float *xin, *partial;
    cudaGetSymbolAddress((void**)&xin, g_xin);
    cudaGetSymbolAddress((void**)&partial, g_partial);

    const int SMEM_CONV4 = 2 * (2*128*144 + 128*144);            // 110592
    const int SMEM_CONV2 = 2 * (2*64*144 + 128*144);             // 73728
    const int SMEM_GMM1  = 2 * (2*64*112 + 160*112);             // 64512
    const int SMEM_GMM2  = 2 * (2*128*112 + 160*112);            // 93184
    cudaFuncSetAttribute(conv_mma<4>, cudaFuncAttributeMaxDynamicSharedMemorySize, SMEM_CONV4);
    cudaFuncSetAttribute(conv_mma<2>, cudaFuncAttributeMaxDynamicSharedMemorySize, SMEM_CONV2);
    cudaFuncSetAttribute(gmm_mma<1>, cudaFuncAttributeMaxDynamicSharedMemorySize, SMEM_GMM1);
    cudaFuncSetAttribute(gmm_mma<2>, cudaFuncAttributeMaxDynamicSharedMemorySize, SMEM_GMM2);

    adj_kernel<<<BB*TT, 256>>>(X);
    bn_stats<<<VC, 256>>>(X, gamma, beta);
    bn_apply<<<(BB*TT*VV*CC0 + 255) / 256, 256>>>(X);

    // conv0: 3 -> 64 (CUDA cores, no relu) -> split fp16 gmm input
    conv0_kernel<<<dim3(TT, BB), 256>>>(xin, w0, b0);

    // layer 1: gmm(64) -> conv 64->64 (+relu), M=64 tiles
    gmm_mma<1><<<BB*TT, 256, SMEM_GMM1>>>();
    wprep<<<(9*64*64 + 255)/256, 256>>>(w1, 64, 64, 64);
    conv_mma<2><<<dim3(NT, BB), 256, SMEM_CONV2>>>(b1, nullptr, 64, 64, 64, 1);

    // layer 2: gmm(64) -> conv 64->128 (+relu)
    gmm_mma<1><<<BB*TT, 256, SMEM_GMM1>>>();
    wprep<<<(9*128*64 + 255)/256, 256>>>(w2, 64, 128, 128);
    conv_mma<4><<<dim3(NT, BB), 256, SMEM_CONV4>>>(b2, nullptr, 64, 128, 128, 1);

    // layer 3: gmm(128) -> conv 128->256 (+relu, fused pooling partials)
    // o-tiles interleaved in grid.x so paired CTAs share B tiles in L2
    gmm_mma<2><<<BB*TT, 256, SMEM_GMM2>>>();
    wprep<<<(9*256*128 + 255)/256, 256>>>(w3, 128, 256, 256);
    conv_mma<4><<<dim3(NT*2, BB), 256, SMEM_CONV4>>>(b3, partial, 128, 256, 256, 2);

    pool_reduce<<<BB, 256>>>();
    fc_kernel<<<BB, 256>>>(fw, fb, out);
}

// round 16
// speedup vs baseline: 1.0000x; 1.0000x over previous
#include <cuda_runtime.h>
#include <cuda_fp16.h>
#include <cstdint>

#define BB 16
#define TT 128
#define VV 137
#define CC0 3
#define PADK 4
#define NCLS 226
#define VC (VV*CC0)       // 411
#define TVN (TT*VV)       // 17536 = 137 * 128
#define NPAD 18816        // 548 halo + 17536 + 548 halo + slack
#define HALO 548
#define NT 137            // conv n-tiles of 128
#define VPAD 144          // gmm K/N padding
#define WPAD 160          // gmm N padding (warp tile 80 x 2)

// ---------------- scratch (static device memory; no allocations) ----------------
__device__ __half g_xT[(size_t)BB*NPAD*128];          // conv B operand (single fp16)
__device__ __half g_xgh[(size_t)BB*TT*128*VPAD];      // gmm A operand (hi)
__device__ __half g_xgl[(size_t)BB*TT*128*VPAD];      // gmm A operand (lo)
__device__ __half g_A[(size_t)BB*TT*WPAD*VPAD];       // adjacency (single fp16)
__device__ float g_xin[(size_t)BB*CC0*TT*VV];
__device__ __half g_wh[9*256*128];
__device__ __half g_wl[9*256*128];
__device__ float g_partial[(size_t)BB*256*NT*4];
__device__ float g_scale[VC];
__device__ float g_shift[VC];
__device__ float g_pooled[BB*256];

// ======================= warp-MMA helpers (compute_103-safe) ====================
__device__ __forceinline__ uint32_t smem_to_u32(const void* p) {
    uint32_t a;
    asm("{ .reg .u64 t; cvta.to.shared.u64 t, %1; cvt.u32.u64 %0, t; }" : "=r"(a) : "l"(p));
    return a;
}
__device__ __forceinline__ void ldsm4(uint32_t* r, uint32_t addr) {
    asm volatile("ldmatrix.sync.aligned.m8n8.x4.shared.b16 {%0,%1,%2,%3}, [%4];"
        : "=r"(r[0]), "=r"(r[1]), "=r"(r[2]), "=r"(r[3]) : "r"(addr));
}
__device__ __forceinline__ void mma_f16(float* d, const uint32_t* a,
                                        uint32_t b0, uint32_t b1) {
    asm volatile("mma.sync.aligned.m16n8k16.row.col.f32.f16.f16.f32 "
        "{%0,%1,%2,%3}, {%4,%5,%6,%7}, {%8,%9}, {%0,%1,%2,%3};"
        : "+f"(d[0]), "+f"(d[1]), "+f"(d[2]), "+f"(d[3])
        : "r"(a[0]), "r"(a[1]), "r"(a[2]), "r"(a[3]), "r"(b0), "r"(b1));
}
__device__ __forceinline__ void split_f16(float v, __half& h, __half& l) {
    h = __float2half_rn(v);
    l = __float2half_rn(v - __half2float(h));
}
__device__ __forceinline__ void cpa16(uint32_t dst, const void* src) {
    asm volatile("cp.async.cg.shared.global [%0], [%1], 16;" :: "r"(dst), "l"(src));
}
#define CP_COMMIT() asm volatile("cp.async.commit_group;" ::: "memory")
#define CP_WAIT1()  asm volatile("cp.async.wait_group 1;" ::: "memory")
#define CP_WAIT0()  asm volatile("cp.async.wait_group 0;" ::: "memory")

// ---------------- adjacency -> fp16 [bt][w(WPAD)][v(VPAD)] ----------------------
__global__ __launch_bounds__(256) void adj_kernel(const float* __restrict__ X) {
    int bt = blockIdx.x;
    __shared__ float px[VV*3];
    const float* src = X + (size_t)bt * VV * CC0;
    for (int i = threadIdx.x; i < VV*3; i += 256) px[i] = src[i];
    __syncthreads();
    const size_t base = (size_t)bt * WPAD * VPAD;
    for (int i = threadIdx.x; i < VV*VV; i += 256) {
        int w = i / VV, v = i % VV;
        float dx = px[v*3+0] - px[w*3+0];
        float dy = px[v*3+1] - px[w*3+1];
        float dz = px[v*3+2] - px[w*3+2];
        float d = sqrtf(dx*dx + dy*dy + dz*dz);
        g_A[base + (size_t)w * VPAD + v] = __float2half_rn(__expf(-2.0f * d));
    }
}

// ---------------- BN stats / apply ----------------------------------------------
__global__ __launch_bounds__(256) void bn_stats(const float* __restrict__ X,
                                                const float* __restrict__ gamma,
                                                const float* __restrict__ beta) {
    int ch = blockIdx.x;
    int v = ch / CC0, c = ch % CC0;
    float s = 0.f, s2 = 0.f;
    for (int i = threadIdx.x; i < BB*TT; i += 256) {
        float x = X[((size_t)i * VV + v) * CC0 + c];
        s += x; s2 += x * x;
    }
    __shared__ float sh1[8], sh2[8];
    int lane = threadIdx.x & 31, wid = threadIdx.x >> 5;
    #pragma unroll
    for (int o = 16; o > 0; o >>= 1) {
        s  += __shfl_xor_sync(0xffffffffu, s, o);
        s2 += __shfl_xor_sync(0xffffffffu, s2, o);
    }
    if (lane == 0) { sh1[wid] = s; sh2[wid] = s2; }
    __syncthreads();
    if (wid == 0) {
        s  = (lane < 8) ? sh1[lane] : 0.f;
        s2 = (lane < 8) ? sh2[lane] : 0.f;
        #pragma unroll
        for (int o = 4; o > 0; o >>= 1) {
            s  += __shfl_xor_sync(0xffffffffu, s, o);
            s2 += __shfl_xor_sync(0xffffffffu, s2, o);
        }
        if (lane == 0) {
            float inv = 1.0f / (BB*TT);
            float mean = s * inv;
            float var = s2 * inv - mean * mean;
            float sc = gamma[ch] * rsqrtf(var + 1e-5f);
            g_scale[ch] = sc;
            g_shift[ch] = beta[ch] - mean * sc;
        }
    }
}

__global__ __launch_bounds__(256) void bn_apply(const float* __restrict__ X) {
    int idx = blockIdx.x * 256 + threadIdx.x;
    if (idx >= BB*TT*VV*CC0) return;
    int c = idx % CC0;
    int v = (idx / CC0) % VV;
    int t = (idx / (CC0*VV)) % TT;
    int b = idx / (CC0*VV*TT);
    int ch = v * CC0 + c;
    g_xin[(((size_t)b * CC0 + c) * TT + t) * VV + v] = X[idx] * g_scale[ch] + g_shift[ch];
}

// ---------------- conv0 (tiny, CUDA cores, Cin=3, no relu) -----------------------
__global__ __launch_bounds__(256) void conv0_kernel(const float* __restrict__ x,
                                                    const float* __restrict__ w,
                                                    const float* __restrict__ bias) {
    const int t = blockIdx.x, b = blockIdx.y;
    __shared__ float ws[3*9*64];
    __shared__ float xs[3*9*160];
    const int tid = threadIdx.x;
    const int vg = tid & 31, og = tid >> 5;
    unsigned long long acc[4][5];
    #pragma unroll
    for (int u = 0; u < 4; u++)
        #pragma unroll
        for (int j = 0; j < 5; j++) acc[u][j] = 0ull;
    for (int i = tid; i < 3*9*64; i += 256) {
        int o = i & 63; int r = i >> 6; int k = r % 9; int ci = r / 9;
        ws[i] = w[((size_t)o * 3 + ci) * 9 + k];
    }
    for (int i = tid; i < 3*9*160; i += 256) {
        int v = i % 160; int r = i / 160; int k = r % 9; int ci = r / 9;
        int tt = t + k - PADK;
        float val = 0.f;
        if (v < VV && tt >= 0 && tt < TT)
            val = x[(((size_t)b * 3 + ci) * TT + tt) * VV + v];
        xs[i] = val;
    }
    __syncthreads();
    #pragma unroll
    for (int ci = 0; ci < 3; ci++) {
        #pragma unroll
        for (int k = 0; k < 9; k++) {
            const float* xrow = &xs[(ci*9 + k) * 160];
            const float* wrow = &ws[(ci*9 + k) * 64 + og * 8];
            unsigned long long xv2[5];
            #pragma unroll
            for (int j = 0; j < 5; j++) {
                float xv = xrow[vg + 32*j];
                asm("mov.b64 %0, {%1,%1};" : "=l"(xv2[j]) : "f"(xv));
            }
            #pragma unroll
            for (int u = 0; u < 4; u++) {
                unsigned long long w2 = *reinterpret_cast<const unsigned long long*>(&wrow[2*u]);
                #pragma unroll
                for (int j = 0; j < 5; j++)
                    asm("fma.rn.f32x2 %0, %1, %2, %0;" : "+l"(acc[u][j]) : "l"(w2), "l"(xv2[j]));
            }
        }
    }
    const size_t rb = (size_t)(b * TT + t) * 128;
    #pragma unroll
    for (int u = 0; u < 4; u++) {
        int o_lo = og*8 + 2*u;
        float b_lo = bias[o_lo], b_hi = bias[o_lo + 1];
        #pragma unroll
        for (int j = 0; j < 5; j++) {
            int v = vg + 32*j;
            if (v < VV) {
                float lo, hi;
                asm("mov.b64 {%0,%1}, %2;" : "=f"(lo), "=f"(hi) : "l"(acc[u][j]));
                lo += b_lo; hi += b_hi;
                __half h, l;
                split_f16(lo, h, l);
                size_t a0 = (rb + o_lo) * VPAD + v;
                g_xgh[a0] = h; g_xgl[a0] = l;
                split_f16(hi, h, l);
                size_t a1 = (rb + o_lo + 1) * VPAD + v;
                g_xgh[a1] = h; g_xgl[a1] = l;
            }
        }
    }
}

// ---------------- gmm_mma: per (b,t) D[c,w] = sum_v x[c,v] * A[w,v] --------------
// A-side: x split fp16 (2-term). B-side: adjacency single fp16.
template<int MFRAG>   // 1: Cin=64, 2: Cin=128
__global__ void __launch_bounds__(256, 1) gmm_mma() {
    extern __shared__ __align__(16) char smem[];
    const uint32_t sb = smem_to_u32(smem);
    const int Cin = MFRAG * 64;
    const int MT = MFRAG * 16;
    const uint32_t XSZ = (uint32_t)Cin * 112;
    const uint32_t ASZ = 160 * 112;
    const uint32_t STAGE = 2*XSZ + ASZ;
    const int bt = blockIdx.x;
    const int b = bt >> 7, t = bt & 127;
    const int tid = threadIdx.x, lane = tid & 31, wid = tid >> 5;
    const int wm = wid >> 1, wn = wid & 1;

    float acc[MFRAG][10][4];
    #pragma unroll
    for (int mi = 0; mi < MFRAG; mi++)
        #pragma unroll
        for (int n = 0; n < 10; n++)
            #pragma unroll
            for (int r = 0; r < 4; r++) acc[mi][n][r] = 0.f;

    const uint32_t a_lane = (uint32_t)(wm*MT + (lane & 15)) * 112 + (uint32_t)(lane >> 4) * 16;
    const uint32_t b_lane = (uint32_t)(wn*80 + (lane & 7) + ((lane >> 4) << 3)) * 112
                          + (uint32_t)((lane >> 3) & 1) * 16;

    auto prefetch = [&](int s) {
        const uint32_t st = sb + (uint32_t)(s & 1) * STAGE;
        const int k0 = s * 48;
        for (int i = tid; i < Cin*6; i += 256) {
            int r = i / 6, j = i % 6;
            uint32_t dst = st + (uint32_t)r * 112 + (uint32_t)j * 16;
            size_t src = ((size_t)bt * 128 + r) * VPAD + k0 + j * 8;
            cpa16(dst, g_xgh + src);
            cpa16(dst + XSZ, g_xgl + src);
        }
        for (int i = tid; i < 160*6; i += 256) {
            int r = i / 6, j = i % 6;
            uint32_t dst = st + 2*XSZ + (uint32_t)r * 112 + (uint32_t)j * 16;
            size_t src = ((size_t)bt * WPAD + r) * VPAD + k0 + j * 8;
            cpa16(dst, g_A + src);
        }
        CP_COMMIT();
    };

    prefetch(0);
    for (int s = 0; s < 3; s++) {
        if (s + 1 < 3) { prefetch(s + 1); CP_WAIT1(); } else { CP_WAIT0(); }
        __syncthreads();
        const uint32_t st = sb + (uint32_t)(s & 1) * STAGE;
        #pragma unroll
        for (int kk = 0; kk < 3; kk++) {
            const uint32_t koff = (uint32_t)kk * 32;
            uint32_t ah[MFRAG][4], al[MFRAG][4];
            #pragma unroll
            for (int mi = 0; mi < MFRAG; mi++) {
                uint32_t ao = a_lane + (uint32_t)mi * (16*112) + koff;
                ldsm4(ah[mi], st + ao);
                ldsm4(al[mi], st + XSZ + ao);
            }
            #pragma unroll
            for (int g = 0; g < 5; g++) {
                uint32_t bv[4];
                uint32_t bo = b_lane + (uint32_t)g * (16*112) + koff;
                ldsm4(bv, st + 2*XSZ + bo);
                #pragma unroll
                for (int mi = 0; mi < MFRAG; mi++)
                    #pragma unroll
                    for (int hh = 0; hh < 2; hh++) {
                        float* d = acc[mi][g*2 + hh];
                        mma_f16(d, ah[mi], bv[2*hh], bv[2*hh+1]);
                        mma_f16(d, al[mi], bv[2*hh], bv[2*hh+1]);
                    }
            }
        }
        __syncthreads();
    }

    // epilogue: write single fp16 g_xT[(b*NPAD + HALO + t*137 + w)*128 + c]
    const int mrow = lane >> 2, nc = (lane & 3) * 2;
    const size_t nbase = (size_t)b * NPAD + HALO + (size_t)t * VV;
    #pragma unroll
    for (int mi = 0; mi < MFRAG; mi++)
        #pragma unroll
        for (int h = 0; h < 2; h++) {
            int c = wm*MT + mi*16 + h*8 + mrow;
            #pragma unroll
            for (int g = 0; g < 5; g++)
                #pragma unroll
                for (int hh = 0; hh < 2; hh++)
                    #pragma unroll
                    for (int e = 0; e < 2; e++) {
                        int w = wn*80 + g*16 + hh*8 + nc + e;
                        if (w < VV)
                            g_xT[(nbase + w) * 128 + c] =
                                __float2half_rn(acc[mi][g*2+hh][h*2+e]);
                    }
        }
}

// ---------------- weight prep: fp32 [o][ci][k] -> split fp16 [k][OPAD][ci] ------
__global__ __launch_bounds__(256) void wprep(const float* __restrict__ w,
                                             int Cin, int Cout, int OPAD) {
    int idx = blockIdx.x * 256 + threadIdx.x;
    int total = 9 * OPAD * Cin;
    if (idx >= total) return;
    int ci = idx % Cin;
    int r = idx / Cin;
    int o = r % OPAD;
    int k = r / OPAD;
    float v = (o < Cout) ? w[((size_t)o * Cin + ci) * 9 + k] : 0.f;
    __half h, l; split_f16(v, h, l);
    g_wh[idx] = h; g_wl[idx] = l;
}

// ---------------- warp-MMA temporal conv, cp.async double-buffered --------------
// A-side: weights split fp16 (2-term). B-side: activations single fp16.
// M = MI*32 (o), N = 128 (n). 8 warps = 2(M) x 4(N).
template<int MI>   // 2: M=64 (layer1), 4: M=128 (layers 2/3)
__global__ void __launch_bounds__(256, 1) conv_mma(
    const float* __restrict__ bias, float* __restrict__ pout,
    int Cin, int Cout, int OPAD, int otiles)
{
    extern __shared__ __align__(16) char smem[];
    const uint32_t sb = smem_to_u32(smem);
    const int AROWS = MI * 32;
    const uint32_t ASZ = (uint32_t)AROWS * 144;
    const uint32_t BSZ = 128 * 144;
    const uint32_t STAGE = 2*ASZ + BSZ;
    const int tid = threadIdx.x;
    const int tileid = blockIdx.x / otiles;            // n tile
    const int o0 = (blockIdx.x - tileid * otiles) * AROWS;
    const int n0 = tileid * 128;
    const int b  = blockIdx.y;
    const int lane = tid & 31, wid = tid >> 5;
    const int wm = wid >> 2, wn = wid & 3;
    const int numC = Cin >> 6;
    const int S = 9 * numC;

    float acc[MI][4][4];
    #pragma unroll
    for (int mi = 0; mi < MI; mi++)
        #pragma unroll
        for (int ni = 0; ni < 4; ni++)
            #pragma unroll
            for (int r = 0; r < 4; r++) acc[mi][ni][r] = 0.f;

    const uint32_t a_lane = (uint32_t)(wm*(MI*16) + (lane & 15)) * 144 + (uint32_t)(lane >> 4) * 16;
    const uint32_t b_lane = (uint32_t)(wn*32 + (lane & 7) + ((lane >> 4) << 3)) * 144
                          + (uint32_t)((lane >> 3) & 1) * 16;

    auto prefetch = [&](int s) {
        const uint32_t st = sb + (uint32_t)(s & 1) * STAGE;
        const int k = s / numC;
        const int c0 = (s - k * numC) << 6;
        const long long brow = (long long)b * NPAD + HALO + n0 + (long long)(k - 4) * VV;
        for (int i = tid; i < AROWS*8; i += 256) {
            int r = i >> 3, ch = i & 7;
            uint32_t dst = st + (uint32_t)r * 144 + (uint32_t)ch * 16;
            size_t src = (size_t)(k * OPAD + o0 + r) * Cin + c0 + ch * 8;
            cpa16(dst, g_wh + src);
            cpa16(dst + ASZ, g_wl + src);
        }
        for (int i = tid; i < 128*8; i += 256) {
            int r = i >> 3, ch = i & 7;
            uint32_t dst = st + 2*ASZ + (uint32_t)r * 144 + (uint32_t)ch * 16;
            size_t src = (size_t)(brow + r) * 128 + c0 + ch * 8;
            cpa16(dst, g_xT + src);
        }
        CP_COMMIT();
    };

    prefetch(0);
    for (int s = 0; s < S; s++) {
        if (s + 1 < S) { prefetch(s + 1); CP_WAIT1(); } else { CP_WAIT0(); }
        __syncthreads();
        const uint32_t st = sb + (uint32_t)(s & 1) * STAGE;
        #pragma unroll
        for (int kk = 0; kk < 4; kk++) {
            const uint32_t koff = (uint32_t)kk * 32;
            uint32_t ah[MI][4], al[MI][4];
            #pragma unroll
            for (int mi = 0; mi < MI; mi++) {
                uint32_t ao = a_lane + (uint32_t)mi * (16*144) + koff;
                ldsm4(ah[mi], st + ao);
                ldsm4(al[mi], st + ASZ + ao);
            }
            uint32_t bv[2][4];
            #pragma unroll
            for (int g = 0; g < 2; g++) {
                uint32_t bo = b_lane + (uint32_t)g * (16*144) + koff;
                ldsm4(bv[g], st + 2*ASZ + bo);
            }
            #pragma unroll
            for (int mi = 0; mi < MI; mi++)
                #pragma unroll
                for (int g = 0; g < 2; g++)
                    #pragma unroll
                    for (int hh = 0; hh < 2; hh++) {
                        int ni = g*2 + hh;
                        mma_f16(acc[mi][ni], ah[mi], bv[g][2*hh], bv[g][2*hh+1]);
                        mma_f16(acc[mi][ni], al[mi], bv[g][2*hh], bv[g][2*hh+1]);
                    }
        }
        __syncthreads();
    }

    const int mrow = lane >> 2;
    const int ncol = (lane & 3) * 2;
    if (pout) {
        // layer 3: bias + relu + pooled partials per (b, o, tile, wn)
        #pragma unroll
        for (int mi = 0; mi < MI; mi++)
            #pragma unroll
            for (int h = 0; h < 2; h++) {
                int o = o0 + wm*(MI*16) + mi*16 + mrow + h*8;
                float bo = bias[o];
                float s = 0.f;
                #pragma unroll
                for (int ni = 0; ni < 4; ni++) {
                    s += fmaxf(acc[mi][ni][2*h+0] + bo, 0.f);
                    s += fmaxf(acc[mi][ni][2*h+1] + bo, 0.f);
                }
                s += __shfl_xor_sync(0xffffffffu, s, 1);
                s += __shfl_xor_sync(0xffffffffu, s, 2);
                if ((lane & 3) == 0)
                    pout[((size_t)(b * 256 + o) * NT + tileid) * 4 + wn] = s;
            }
    } else {
        // layers 1/2: bias + relu, write split fp16 x[bt][c][VPAD] for next gmm
        #pragma unroll
        for (int mi = 0; mi < MI; mi++)
            #pragma unroll
            for (int h = 0; h < 2; h++) {
                int o = o0 + wm*(MI*16) + mi*16 + mrow + h*8;
                if (o < Cout) {
                    float bo = bias[o];
                    #pragma unroll
                    for (int ni = 0; ni < 4; ni++)
                        #pragma unroll
                        for (int e = 0; e < 2; e++) {
                            int n = n0 + wn*32 + ni*8 + ncol + e;
                            float val = fmaxf(acc[mi][ni][2*h+e] + bo, 0.f);
                            __half hv, lv; split_f16(val, hv, lv);
                            int tt = n / VV, v = n - tt * VV;
                            size_t ad = ((size_t)(b * TT + tt) * 128 + o) * VPAD + v;
                            g_xgh[ad] = hv; g_xgl[ad] = lv;
                        }
                }
            }
    }
}

// ---------------- pool reduce + FC -----------------------------------------------
__global__ __launch_bounds__(256) void pool_reduce() {
    int idx = blockIdx.x * 256 + threadIdx.x;
    if (idx >= BB * 256) return;
    const float* p = &g_partial[(size_t)idx * NT * 4];
    float s = 0.f;
    for (int i = 0; i < NT * 4; i++) s += p[i];
    g_pooled[idx] = s * (1.0f / TVN);
}

__global__ __launch_bounds__(256) void fc_kernel(const float* __restrict__ fw,
                                                 const float* __restrict__ fb,
                                                 float* __restrict__ out) {
    int b = blockIdx.x;
    __shared__ float ps[256];
    ps[threadIdx.x] = g_pooled[b * 256 + threadIdx.x];
    __syncthreads();
    int n = threadIdx.x;
    if (n < NCLS) {
        float s = fb[n];
        const float* wr = &fw[(size_t)n * 256];
        #pragma unroll 8
        for (int c = 0; c < 256; c++) s += ps[c] * wr[c];
        out[b * NCLS + n] = s;
    }
}

// ---------------- launch ----------------------------------------------------------
extern "C" void kernel_launch(void* const* d_in, const int* in_sizes, int n_in,
                              void* d_out, int out_size) {
    const float* X     = (const float*)d_in[0];
    const float* gamma = (const float*)d_in[1];
    const float* beta  = (const float*)d_in[2];
    const float* w0 = (const float*)d_in[3];  const float* b0 = (const float*)d_in[4];
    const float* w1 = (const float*)d_in[5];  const float* b1 = (const float*)d_in[6];
    const float* w2 = (const float*)d_in[7];  const float* b2 = (const float*)d_in[8];
    const float* w3 = (const float*)d_in[9];  const float* b3 = (const float*)d_in[10];
    const float* fw = (const float*)d_in[11]; const float* fb = (const float*)d_in[12];
    float* out = (float*)d_out;

    float *xin, *partial;
    cudaGetSymbolAddress((void**)&xin, g_xin);
    cudaGetSymbolAddress((void**)&partial, g_partial);

    const int SMEM_CONV4 = 2 * (2*128*144 + 128*144);            // 110592
    const int SMEM_CONV2 = 2 * (2*64*144 + 128*144);             // 73728
    const int SMEM_GMM1  = 2 * (2*64*112 + 160*112);             // 64512
    const int SMEM_GMM2  = 2 * (2*128*112 + 160*112);            // 93184
    cudaFuncSetAttribute(conv_mma<4>, cudaFuncAttributeMaxDynamicSharedMemorySize, SMEM_CONV4);
    cudaFuncSetAttribute(conv_mma<2>, cudaFuncAttributeMaxDynamicSharedMemorySize, SMEM_CONV2);
    cudaFuncSetAttribute(gmm_mma<1>, cudaFuncAttributeMaxDynamicSharedMemorySize, SMEM_GMM1);
    cudaFuncSetAttribute(gmm_mma<2>, cudaFuncAttributeMaxDynamicSharedMemorySize, SMEM_GMM2);

    adj_kernel<<<BB*TT, 256>>>(X);
    bn_stats<<<VC, 256>>>(X, gamma, beta);
    bn_apply<<<(BB*TT*VV*CC0 + 255) / 256, 256>>>(X);

    // conv0: 3 -> 64 (CUDA cores, no relu) -> split fp16 gmm input
    conv0_kernel<<<dim3(TT, BB), 256>>>(xin, w0, b0);

    // layer 1: gmm(64) -> conv 64->64 (+relu), M=64 tiles
    gmm_mma<1><<<BB*TT, 256, SMEM_GMM1>>>();
    wprep<<<(9*64*64 + 255)/256, 256>>>(w1, 64, 64, 64);
    conv_mma<2><<<dim3(NT, BB), 256, SMEM_CONV2>>>(b1, nullptr, 64, 64, 64, 1);

    // layer 2: gmm(64) -> conv 64->128 (+relu)
    gmm_mma<1><<<BB*TT, 256, SMEM_GMM1>>>();
    wprep<<<(9*128*64 + 255)/256, 256>>>(w2, 64, 128, 128);
    conv_mma<4><<<dim3(NT, BB), 256, SMEM_CONV4>>>(b2, nullptr, 64, 128, 128, 1);

    // layer 3: gmm(128) -> conv 128->256 (+relu, fused pooling partials)
    // o-tiles interleaved in grid.x so paired CTAs share B tiles in L2
    gmm_mma<2><<<BB*TT, 256, SMEM_GMM2>>>();
    wprep<<<(9*256*128 + 255)/256, 256>>>(w3, 128, 256, 256);
    conv_mma<4><<<dim3(NT*2, BB), 256, SMEM_CONV4>>>(b3, partial, 128, 256, 256, 2);

    pool_reduce<<<BB, 256>>>();
    fc_kernel<<<BB, 256>>>(fw, fb, out);
}

// round 17
// speedup vs baseline: 1.0001x; 1.0001x over previous
#include <cuda_runtime.h>
#include <cuda_fp16.h>
#include <cstdint>

#define BB 16
#define TT 128
#define VV 137
#define CC0 3
#define PADK 4
#define NCLS 226
#define VC (VV*CC0)       // 411
#define TVN (TT*VV)       // 17536 = 137 * 128
#define NPAD 18816        // 548 halo + 17536 + 548 halo + slack
#define HALO 548
#define NT 137            // conv n-tiles of 128
#define VPAD 144          // gmm K/N padding
#define WPAD 160          // gmm N padding (warp tile 80 x 2)

// ---------------- scratch (static device memory; no allocations) ----------------
__device__ __half g_xT[(size_t)BB*NPAD*128];          // conv B operand (single fp16)
__device__ __half g_xgh[(size_t)BB*TT*128*VPAD];      // gmm A operand (hi)
__device__ __half g_xgl[(size_t)BB*TT*128*VPAD];      // gmm A operand (lo)
__device__ __half g_A[(size_t)BB*TT*WPAD*VPAD];       // adjacency (single fp16)
__device__ float g_xin[(size_t)BB*CC0*TT*VV];
__device__ __half g_wh[9*256*128];
__device__ __half g_wl[9*256*128];
__device__ float g_partial[(size_t)BB*256*NT*4];
__device__ float g_scale[VC];
__device__ float g_shift[VC];
__device__ float g_pooled[BB*256];

// ======================= warp-MMA helpers (compute_103-safe) ====================
__device__ __forceinline__ uint32_t smem_to_u32(const void* p) {
    uint32_t a;
    asm("{ .reg .u64 t; cvta.to.shared.u64 t, %1; cvt.u32.u64 %0, t; }" : "=r"(a) : "l"(p));
    return a;
}
__device__ __forceinline__ void ldsm4(uint32_t* r, uint32_t addr) {
    asm volatile("ldmatrix.sync.aligned.m8n8.x4.shared.b16 {%0,%1,%2,%3}, [%4];"
        : "=r"(r[0]), "=r"(r[1]), "=r"(r[2]), "=r"(r[3]) : "r"(addr));
}
__device__ __forceinline__ void mma_f16(float* d, const uint32_t* a,
                                        uint32_t b0, uint32_t b1) {
    asm volatile("mma.sync.aligned.m16n8k16.row.col.f32.f16.f16.f32 "
        "{%0,%1,%2,%3}, {%4,%5,%6,%7}, {%8,%9}, {%0,%1,%2,%3};"
        : "+f"(d[0]), "+f"(d[1]), "+f"(d[2]), "+f"(d[3])
        : "r"(a[0]), "r"(a[1]), "r"(a[2]), "r"(a[3]), "r"(b0), "r"(b1));
}
__device__ __forceinline__ void split_f16(float v, __half& h, __half& l) {
    h = __float2half_rn(v);
    l = __float2half_rn(v - __half2float(h));
}
__device__ __forceinline__ void cpa16(uint32_t dst, const void* src) {
    asm volatile("cp.async.cg.shared.global [%0], [%1], 16;" :: "r"(dst), "l"(src));
}
#define CP_COMMIT() asm volatile("cp.async.commit_group;" ::: "memory")
#define CP_WAIT1()  asm volatile("cp.async.wait_group 1;" ::: "memory")
#define CP_WAIT0()  asm volatile("cp.async.wait_group 0;" ::: "memory")

// ---------------- adjacency -> fp16 [bt][w(WPAD)][v(VPAD)] ----------------------
__global__ __launch_bounds__(256) void adj_kernel(const float* __restrict__ X) {
    int bt = blockIdx.x;
    __shared__ float px[VV*3];
    const float* src = X + (size_t)bt * VV * CC0;
    for (int i = threadIdx.x; i < VV*3; i += 256) px[i] = src[i];
    __syncthreads();
    const size_t base = (size_t)bt * WPAD * VPAD;
    for (int i = threadIdx.x; i < VV*VV; i += 256) {
        int w = i / VV, v = i % VV;
        float dx = px[v*3+0] - px[w*3+0];
        float dy = px[v*3+1] - px[w*3+1];
        float dz = px[v*3+2] - px[w*3+2];
        float d = sqrtf(dx*dx + dy*dy + dz*dz);
        g_A[base + (size_t)w * VPAD + v] = __float2half_rn(__expf(-2.0f * d));
    }
}

// ---------------- BN stats / apply ----------------------------------------------
__global__ __launch_bounds__(256) void bn_stats(const float* __restrict__ X,
                                                const float* __restrict__ gamma,
                                                const float* __restrict__ beta) {
    int ch = blockIdx.x;
    int v = ch / CC0, c = ch % CC0;
    float s = 0.f, s2 = 0.f;
    for (int i = threadIdx.x; i < BB*TT; i += 256) {
        float x = X[((size_t)i * VV + v) * CC0 + c];
        s += x; s2 += x * x;
    }
    __shared__ float sh1[8], sh2[8];
    int lane = threadIdx.x & 31, wid = threadIdx.x >> 5;
    #pragma unroll
    for (int o = 16; o > 0; o >>= 1) {
        s  += __shfl_xor_sync(0xffffffffu, s, o);
        s2 += __shfl_xor_sync(0xffffffffu, s2, o);
    }
    if (lane == 0) { sh1[wid] = s; sh2[wid] = s2; }
    __syncthreads();
    if (wid == 0) {
        s  = (lane < 8) ? sh1[lane] : 0.f;
        s2 = (lane < 8) ? sh2[lane] : 0.f;
        #pragma unroll
        for (int o = 4; o > 0; o >>= 1) {
            s  += __shfl_xor_sync(0xffffffffu, s, o);
            s2 += __shfl_xor_sync(0xffffffffu, s2, o);
        }
        if (lane == 0) {
            float inv = 1.0f / (BB*TT);
            float mean = s * inv;
            float var = s2 * inv - mean * mean;
            float sc = gamma[ch] * rsqrtf(var + 1e-5f);
            g_scale[ch] = sc;
            g_shift[ch] = beta[ch] - mean * sc;
        }
    }
}

__global__ __launch_bounds__(256) void bn_apply(const float* __restrict__ X) {
    int idx = blockIdx.x * 256 + threadIdx.x;
    if (idx >= BB*TT*VV*CC0) return;
    int c = idx % CC0;
    int v = (idx / CC0) % VV;
    int t = (idx / (CC0*VV)) % TT;
    int b = idx / (CC0*VV*TT);
    int ch = v * CC0 + c;
    g_xin[(((size_t)b * CC0 + c) * TT + t) * VV + v] = X[idx] * g_scale[ch] + g_shift[ch];
}

// ---------------- conv0 (tiny, CUDA cores, Cin=3, no relu) -----------------------
__global__ __launch_bounds__(256) void conv0_kernel(const float* __restrict__ x,
                                                    const float* __restrict__ w,
                                                    const float* __restrict__ bias) {
    const int t = blockIdx.x, b = blockIdx.y;
    __shared__ float ws[3*9*64];
    __shared__ float xs[3*9*160];
    const int tid = threadIdx.x;
    const int vg = tid & 31, og = tid >> 5;
    unsigned long long acc[4][5];
    #pragma unroll
    for (int u = 0; u < 4; u++)
        #pragma unroll
        for (int j = 0; j < 5; j++) acc[u][j] = 0ull;
    for (int i = tid; i < 3*9*64; i += 256) {
        int o = i & 63; int r = i >> 6; int k = r % 9; int ci = r / 9;
        ws[i] = w[((size_t)o * 3 + ci) * 9 + k];
    }
    for (int i = tid; i < 3*9*160; i += 256) {
        int v = i % 160; int r = i / 160; int k = r % 9; int ci = r / 9;
        int tt = t + k - PADK;
        float val = 0.f;
        if (v < VV && tt >= 0 && tt < TT)
            val = x[(((size_t)b * 3 + ci) * TT + tt) * VV + v];
        xs[i] = val;
    }
    __syncthreads();
    #pragma unroll
    for (int ci = 0; ci < 3; ci++) {
        #pragma unroll
        for (int k = 0; k < 9; k++) {
            const float* xrow = &xs[(ci*9 + k) * 160];
            const float* wrow = &ws[(ci*9 + k) * 64 + og * 8];
            unsigned long long xv2[5];
            #pragma unroll
            for (int j = 0; j < 5; j++) {
                float xv = xrow[vg + 32*j];
                asm("mov.b64 %0, {%1,%1};" : "=l"(xv2[j]) : "f"(xv));
            }
            #pragma unroll
            for (int u = 0; u < 4; u++) {
                unsigned long long w2 = *reinterpret_cast<const unsigned long long*>(&wrow[2*u]);
                #pragma unroll
                for (int j = 0; j < 5; j++)
                    asm("fma.rn.f32x2 %0, %1, %2, %0;" : "+l"(acc[u][j]) : "l"(w2), "l"(xv2[j]));
            }
        }
    }
    const size_t rb = (size_t)(b * TT + t) * 128;
    #pragma unroll
    for (int u = 0; u < 4; u++) {
        int o_lo = og*8 + 2*u;
        float b_lo = bias[o_lo], b_hi = bias[o_lo + 1];
        #pragma unroll
        for (int j = 0; j < 5; j++) {
            int v = vg + 32*j;
            if (v < VV) {
                float lo, hi;
                asm("mov.b64 {%0,%1}, %2;" : "=f"(lo), "=f"(hi) : "l"(acc[u][j]));
                lo += b_lo; hi += b_hi;
                __half h, l;
                split_f16(lo, h, l);
                size_t a0 = (rb + o_lo) * VPAD + v;
                g_xgh[a0] = h; g_xgl[a0] = l;
                split_f16(hi, h, l);
                size_t a1 = (rb + o_lo + 1) * VPAD + v;
                g_xgh[a1] = h; g_xgl[a1] = l;
            }
        }
    }
}

// ---------------- gmm_mma: per (b,t) D[c,w] = sum_v x[c,v] * A[w,v] --------------
// A-side: x split fp16 (2-term). B-side: adjacency single fp16.
template<int MFRAG>   // 1: Cin=64, 2: Cin=128
__global__ void __launch_bounds__(256, 1) gmm_mma() {
    extern __shared__ __align__(16) char smem[];
    const uint32_t sb = smem_to_u32(smem);
    const int Cin = MFRAG * 64;
    const int MT = MFRAG * 16;
    const uint32_t XSZ = (uint32_t)Cin * 112;
    const uint32_t ASZ = 160 * 112;
    const uint32_t STAGE = 2*XSZ + ASZ;
    const int bt = blockIdx.x;
    const int b = bt >> 7, t = bt & 127;
    const int tid = threadIdx.x, lane = tid & 31, wid = tid >> 5;
    const int wm = wid >> 1, wn = wid & 1;

    float acc[MFRAG][10][4];
    #pragma unroll
    for (int mi = 0; mi < MFRAG; mi++)
        #pragma unroll
        for (int n = 0; n < 10; n++)
            #pragma unroll
            for (int r = 0; r < 4; r++) acc[mi][n][r] = 0.f;

    const uint32_t a_lane = (uint32_t)(wm*MT + (lane & 15)) * 112 + (uint32_t)(lane >> 4) * 16;
    const uint32_t b_lane = (uint32_t)(wn*80 + (lane & 7) + ((lane >> 4) << 3)) * 112
                          + (uint32_t)((lane >> 3) & 1) * 16;

    auto prefetch = [&](int s) {
        const uint32_t st = sb + (uint32_t)(s & 1) * STAGE;
        const int k0 = s * 48;
        for (int i = tid; i < Cin*6; i += 256) {
            int r = i / 6, j = i % 6;
            uint32_t dst = st + (uint32_t)r * 112 + (uint32_t)j * 16;
            size_t src = ((size_t)bt * 128 + r) * VPAD + k0 + j * 8;
            cpa16(dst, g_xgh + src);
            cpa16(dst + XSZ, g_xgl + src);
        }
        for (int i = tid; i < 160*6; i += 256) {
            int r = i / 6, j = i % 6;
            uint32_t dst = st + 2*XSZ + (uint32_t)r * 112 + (uint32_t)j * 16;
            size_t src = ((size_t)bt * WPAD + r) * VPAD + k0 + j * 8;
            cpa16(dst, g_A + src);
        }
        CP_COMMIT();
    };

    prefetch(0);
    for (int s = 0; s < 3; s++) {
        if (s + 1 < 3) { prefetch(s + 1); CP_WAIT1(); } else { CP_WAIT0(); }
        __syncthreads();
        const uint32_t st = sb + (uint32_t)(s & 1) * STAGE;
        #pragma unroll
        for (int kk = 0; kk < 3; kk++) {
            const uint32_t koff = (uint32_t)kk * 32;
            uint32_t ah[MFRAG][4], al[MFRAG][4];
            #pragma unroll
            for (int mi = 0; mi < MFRAG; mi++) {
                uint32_t ao = a_lane + (uint32_t)mi * (16*112) + koff;
                ldsm4(ah[mi], st + ao);
                ldsm4(al[mi], st + XSZ + ao);
            }
            #pragma unroll
            for (int g = 0; g < 5; g++) {
                uint32_t bv[4];
                uint32_t bo = b_lane + (uint32_t)g * (16*112) + koff;
                ldsm4(bv, st + 2*XSZ + bo);
                #pragma unroll
                for (int mi = 0; mi < MFRAG; mi++)
                    #pragma unroll
                    for (int hh = 0; hh < 2; hh++) {
                        float* d = acc[mi][g*2 + hh];
                        mma_f16(d, ah[mi], bv[2*hh], bv[2*hh+1]);
                        mma_f16(d, al[mi], bv[2*hh], bv[2*hh+1]);
                    }
            }
        }
        __syncthreads();
    }

    // epilogue: write single fp16 g_xT[(b*NPAD + HALO + t*137 + w)*128 + c]
    const int mrow = lane >> 2, nc = (lane & 3) * 2;
    const size_t nbase = (size_t)b * NPAD + HALO + (size_t)t * VV;
    #pragma unroll
    for (int mi = 0; mi < MFRAG; mi++)
        #pragma unroll
        for (int h = 0; h < 2; h++) {
            int c = wm*MT + mi*16 + h*8 + mrow;
            #pragma unroll
            for (int g = 0; g < 5; g++)
                #pragma unroll
                for (int hh = 0; hh < 2; hh++)
                    #pragma unroll
                    for (int e = 0; e < 2; e++) {
                        int w = wn*80 + g*16 + hh*8 + nc + e;
                        if (w < VV)
                            g_xT[(nbase + w) * 128 + c] =
                                __float2half_rn(acc[mi][g*2+hh][h*2+e]);
                    }
        }
}

// ---------------- weight prep: fp32 [o][ci][k] -> split fp16 [k][OPAD][ci] ------
__global__ __launch_bounds__(256) void wprep(const float* __restrict__ w,
                                             int Cin, int Cout, int OPAD) {
    int idx = blockIdx.x * 256 + threadIdx.x;
    int total = 9 * OPAD * Cin;
    if (idx >= total) return;
    int ci = idx % Cin;
    int r = idx / Cin;
    int o = r % OPAD;
    int k = r / OPAD;
    float v = (o < Cout) ? w[((size_t)o * Cin + ci) * 9 + k] : 0.f;
    __half h, l; split_f16(v, h, l);
    g_wh[idx] = h; g_wl[idx] = l;
}

// ---------------- warp-MMA temporal conv, cp.async double-buffered --------------
// A-side: weights split fp16 (2-term). B-side: activations single fp16.
// M = MI*32 (o), N = 128 (n). 8 warps = 2(M) x 4(N).
template<int MI>   // 2: M=64 (layer1), 4: M=128 (layers 2/3)
__global__ void __launch_bounds__(256, 1) conv_mma(
    const float* __restrict__ bias, float* __restrict__ pout,
    int Cin, int Cout, int OPAD, int otiles)
{
    extern __shared__ __align__(16) char smem[];
    const uint32_t sb = smem_to_u32(smem);
    const int AROWS = MI * 32;
    const uint32_t ASZ = (uint32_t)AROWS * 144;
    const uint32_t BSZ = 128 * 144;
    const uint32_t STAGE = 2*ASZ + BSZ;
    const int tid = threadIdx.x;
    const int tileid = blockIdx.x / otiles;            // n tile
    const int o0 = (blockIdx.x - tileid * otiles) * AROWS;
    const int n0 = tileid * 128;
    const int b  = blockIdx.y;
    const int lane = tid & 31, wid = tid >> 5;
    const int wm = wid >> 2, wn = wid & 3;
    const int numC = Cin >> 6;
    const int S = 9 * numC;

    float acc[MI][4][4];
    #pragma unroll
    for (int mi = 0; mi < MI; mi++)
        #pragma unroll
        for (int ni = 0; ni < 4; ni++)
            #pragma unroll
            for (int r = 0; r < 4; r++) acc[mi][ni][r] = 0.f;

    const uint32_t a_lane = (uint32_t)(wm*(MI*16) + (lane & 15)) * 144 + (uint32_t)(lane >> 4) * 16;
    const uint32_t b_lane = (uint32_t)(wn*32 + (lane & 7) + ((lane >> 4) << 3)) * 144
                          + (uint32_t)((lane >> 3) & 1) * 16;

    auto prefetch = [&](int s) {
        const uint32_t st = sb + (uint32_t)(s & 1) * STAGE;
        const int k = s / numC;
        const int c0 = (s - k * numC) << 6;
        const long long brow = (long long)b * NPAD + HALO + n0 + (long long)(k - 4) * VV;
        for (int i = tid; i < AROWS*8; i += 256) {
            int r = i >> 3, ch = i & 7;
            uint32_t dst = st + (uint32_t)r * 144 + (uint32_t)ch * 16;
            size_t src = (size_t)(k * OPAD + o0 + r) * Cin + c0 + ch * 8;
            cpa16(dst, g_wh + src);
            cpa16(dst + ASZ, g_wl + src);
        }
        for (int i = tid; i < 128*8; i += 256) {
            int r = i >> 3, ch = i & 7;
            uint32_t dst = st + 2*ASZ + (uint32_t)r * 144 + (uint32_t)ch * 16;
            size_t src = (size_t)(brow + r) * 128 + c0 + ch * 8;
            cpa16(dst, g_xT + src);
        }
        CP_COMMIT();
    };

    prefetch(0);
    for (int s = 0; s < S; s++) {
        if (s + 1 < S) { prefetch(s + 1); CP_WAIT1(); } else { CP_WAIT0(); }
        __syncthreads();
        const uint32_t st = sb + (uint32_t)(s & 1) * STAGE;
        #pragma unroll
        for (int kk = 0; kk < 4; kk++) {
            const uint32_t koff = (uint32_t)kk * 32;
            uint32_t ah[MI][4], al[MI][4];
            #pragma unroll
            for (int mi = 0; mi < MI; mi++) {
                uint32_t ao = a_lane + (uint32_t)mi * (16*144) + koff;
                ldsm4(ah[mi], st + ao);
                ldsm4(al[mi], st + ASZ + ao);
            }
            uint32_t bv[2][4];
            #pragma unroll
            for (int g = 0; g < 2; g++) {
                uint32_t bo = b_lane + (uint32_t)g * (16*144) + koff;
                ldsm4(bv[g], st + 2*ASZ + bo);
            }
            #pragma unroll
            for (int mi = 0; mi < MI; mi++)
                #pragma unroll
                for (int g = 0; g < 2; g++)
                    #pragma unroll
                    for (int hh = 0; hh < 2; hh++) {
                        int ni = g*2 + hh;
                        mma_f16(acc[mi][ni], ah[mi], bv[g][2*hh], bv[g][2*hh+1]);
                        mma_f16(acc[mi][ni], al[mi], bv[g][2*hh], bv[g][2*hh+1]);
                    }
        }
        __syncthreads();
    }

    const int mrow = lane >> 2;
    const int ncol = (lane & 3) * 2;
    if (pout) {
        // layer 3: bias + relu + pooled partials per (b, o, tile, wn)
        #pragma unroll
        for (int mi = 0; mi < MI; mi++)
            #pragma unroll
            for (int h = 0; h < 2; h++) {
                int o = o0 + wm*(MI*16) + mi*16 + mrow + h*8;
                float bo = bias[o];
                float s = 0.f;
                #pragma unroll
                for (int ni = 0; ni < 4; ni++) {
                    s += fmaxf(acc[mi][ni][2*h+0] + bo, 0.f);
                    s += fmaxf(acc[mi][ni][2*h+1] + bo, 0.f);
                }
                s += __shfl_xor_sync(0xffffffffu, s, 1);
                s += __shfl_xor_sync(0xffffffffu, s, 2);
                if ((lane & 3) == 0)
                    pout[((size_t)(b * 256 + o) * NT + tileid) * 4 + wn] = s;
            }
    } else {
        // layers 1/2: bias + relu, write split fp16 x[bt][c][VPAD] for next gmm
        #pragma unroll
        for (int mi = 0; mi < MI; mi++)
            #pragma unroll
            for (int h = 0; h < 2; h++) {
                int o = o0 + wm*(MI*16) + mi*16 + mrow + h*8;
                if (o < Cout) {
                    float bo = bias[o];
                    #pragma unroll
                    for (int ni = 0; ni < 4; ni++)
                        #pragma unroll
                        for (int e = 0; e < 2; e++) {
                            int n = n0 + wn*32 + ni*8 + ncol + e;
                            float val = fmaxf(acc[mi][ni][2*h+e] + bo, 0.f);
                            __half hv, lv; split_f16(val, hv, lv);
                            int tt = n / VV, v = n - tt * VV;
                            size_t ad = ((size_t)(b * TT + tt) * 128 + o) * VPAD + v;
                            g_xgh[ad] = hv; g_xgl[ad] = lv;
                        }
                }
            }
    }
}

// ---------------- pool reduce + FC -----------------------------------------------
__global__ __launch_bounds__(256) void pool_reduce() {
    int idx = blockIdx.x * 256 + threadIdx.x;
    if (idx >= BB * 256) return;
    const float* p = &g_partial[(size_t)idx * NT * 4];
    float s = 0.f;
    for (int i = 0; i < NT * 4; i++) s += p[i];
    g_pooled[idx] = s * (1.0f / TVN);
}

__global__ __launch_bounds__(256) void fc_kernel(const float* __restrict__ fw,
                                                 const float* __restrict__ fb,
                                                 float* __restrict__ out) {
    int b = blockIdx.x;
    __shared__ float ps[256];
    ps[threadIdx.x] = g_pooled[b * 256 + threadIdx.x];
    __syncthreads();
    int n = threadIdx.x;
    if (n < NCLS) {
        float s = fb[n];
        const float* wr = &fw[(size_t)n * 256];
        #pragma unroll 8
        for (int c = 0; c < 256; c++) s += ps[c] * wr[c];
        out[b * NCLS + n] = s;
    }
}

// ---------------- launch ----------------------------------------------------------
extern "C" void kernel_launch(void* const* d_in, const int* in_sizes, int n_in,
                              void* d_out, int out_size) {
    const float* X     = (const float*)d_in[0];
    const float* gamma = (const float*)d_in[1];
    const float* beta  = (const float*)d_in[2];
    const float* w0 = (const float*)d_in[3];  const float* b0 = (const float*)d_in[4];
    const float* w1 = (const float*)d_in[5];  const float* b1 = (const float*)d_in[6];
    const float* w2 = (const float*)d_in[7];  const float* b2 = (const float*)d_in[8];
    const float* w3 = (const float*)d_in[9];  const float* b3 = (const float*)d_in[10];
    const float* fw = (const float*)d_in[11]; const float* fb = (const float*)d_in[12];
    float* out = (float*)d_out;

    float *xin, *partial;
    cudaGetSymbolAddress((void**)&xin, g_xin);
    cudaGetSymbolAddress((void**)&partial, g_partial);

    const int SMEM_CONV4 = 2 * (2*128*144 + 128*144);            // 110592
    const int SMEM_CONV2 = 2 * (2*64*144 + 128*144);             // 73728
    const int SMEM_GMM1  = 2 * (2*64*112 + 160*112);             // 64512
    const int SMEM_GMM2  = 2 * (2*128*112 + 160*112);            // 93184
    cudaFuncSetAttribute(conv_mma<4>, cudaFuncAttributeMaxDynamicSharedMemorySize, SMEM_CONV4);
    cudaFuncSetAttribute(conv_mma<2>, cudaFuncAttributeMaxDynamicSharedMemorySize, SMEM_CONV2);
    cudaFuncSetAttribute(gmm_mma<1>, cudaFuncAttributeMaxDynamicSharedMemorySize, SMEM_GMM1);
    cudaFuncSetAttribute(gmm_mma<2>, cudaFuncAttributeMaxDynamicSharedMemorySize, SMEM_GMM2);

    adj_kernel<<<BB*TT, 256>>>(X);
    bn_stats<<<VC, 256>>>(X, gamma, beta);
    bn_apply<<<(BB*TT*VV*CC0 + 255) / 256, 256>>>(X);

    // conv0: 3 -> 64 (CUDA cores, no relu) -> split fp16 gmm input
    conv0_kernel<<<dim3(TT, BB), 256>>>(xin, w0, b0);

    // layer 1: gmm(64) -> conv 64->64 (+relu), M=64 tiles
    gmm_mma<1><<<BB*TT, 256, SMEM_GMM1>>>();
    wprep<<<(9*64*64 + 255)/256, 256>>>(w1, 64, 64, 64);
    conv_mma<2><<<dim3(NT, BB), 256, SMEM_CONV2>>>(b1, nullptr, 64, 64, 64, 1);

    // layer 2: gmm(64) -> conv 64->128 (+relu)
    gmm_mma<1><<<BB*TT, 256, SMEM_GMM1>>>();
    wprep<<<(9*128*64 + 255)/256, 256>>>(w2, 64, 128, 128);
    conv_mma<4><<<dim3(NT, BB), 256, SMEM_CONV4>>>(b2, nullptr, 64, 128, 128, 1);

    // layer 3: gmm(128) -> conv 128->256 (+relu, fused pooling partials)
    // o-tiles interleaved in grid.x so paired CTAs share B tiles in L2
    gmm_mma<2><<<BB*TT, 256, SMEM_GMM2>>>();
    wprep<<<(9*256*128 + 255)/256, 256>>>(w3, 128, 256, 256);
    conv_mma<4><<<dim3(NT*2, BB), 256, SMEM_CONV4>>>(b3, partial, 128, 256, 256, 2);

    pool_reduce<<<BB, 256>>>();
    fc_kernel<<<BB, 256>>>(fw, fb, out);
}